// round 8
// baseline (speedup 1.0000x reference)
#include <cuda_runtime.h>
#include <cstdint>

// Problem constants
#define B_ 16
#define K_ 49
#define T_ 256
#define H_ 512
#define D_ 512

// Output packing: (c_hat_t, alpha_t, beta_t) flattened in order
#define OUT_ALPHA (B_ * T_ * H_)              // 2097152
#define OUT_BETA  (OUT_ALPHA + B_ * T_ * K_)  // 2297856

// Scratch (device globals: allocation-free)
__device__ float g_cv[B_ * K_ * D_];   // V @ Wv + bv
__device__ float g_cg[B_ * T_ * D_];   // h_t @ Wg + bg
__device__ float g_cs[B_ * T_ * D_];   // s_t @ Ws + bs

// ---------------------------------------------------------------------------
// Merged TF32 mma.sync GEMM: computes all three C[M,512] = A[M,512]@W + bias.
// ---------------------------------------------------------------------------
__global__ __launch_bounds__(256)
void gemm3_tf32_kernel(const float* __restrict__ V, const float* __restrict__ h_t,
                       const float* __restrict__ s_t,
                       const float* __restrict__ Wv, const float* __restrict__ bv,
                       const float* __restrict__ Wg, const float* __restrict__ bg,
                       const float* __restrict__ Wss, const float* __restrict__ bss)
{
    __shared__ float As[128 * 32];     // [m][k], k index xor-swizzled by 4*(m&7)
    __shared__ float Bs[32 * 136];     // [k][n], row stride 136 (pad 8)

    const int nt = blockIdx.x;         // 0..3
    int mt = blockIdx.y;               // 0..70
    const float *A, *W, *bias;
    float* C;
    int M;
    if (mt < 7)       { A = V;   W = Wv;  bias = bv;  C = g_cv; M = B_ * K_; }
    else if (mt < 39) { A = h_t; W = Wg;  bias = bg;  C = g_cg; M = B_ * T_; mt -= 7; }
    else              { A = s_t; W = Wss; bias = bss; C = g_cs; M = B_ * T_; mt -= 39; }

    const int tid  = threadIdx.x;
    const int lane = tid & 31;
    const int wid  = tid >> 5;
    const int g    = lane >> 2;
    const int tg   = lane & 3;
    const int warp_m = (wid >> 2) * 64;
    const int warp_n = (wid & 3) * 32;

    const int mbase = mt * 128;
    const int nbase = nt * 128;

    float acc[4][4][4];
    #pragma unroll
    for (int i = 0; i < 4; i++)
        #pragma unroll
        for (int j = 0; j < 4; j++)
            #pragma unroll
            for (int q = 0; q < 4; q++) acc[i][j][q] = 0.f;

    const int a_m0 = tid >> 3;
    const int a_k4 = (tid & 7) * 4;
    const int w_k0 = tid >> 5;
    const int w_n4 = (tid & 31) * 4;

    float4 pa[4], pw[4];

    #pragma unroll
    for (int i = 0; i < 4; i++) {
        const int row = mbase + a_m0 + i * 32;
        pa[i] = (row < M) ? *reinterpret_cast<const float4*>(&A[(size_t)row * 512 + a_k4])
                          : make_float4(0.f, 0.f, 0.f, 0.f);
        pw[i] = *reinterpret_cast<const float4*>(&W[(size_t)(w_k0 + i * 8) * 512 + nbase + w_n4]);
    }
    #pragma unroll
    for (int i = 0; i < 4; i++) {
        const int m = a_m0 + i * 32;
        *reinterpret_cast<float4*>(&As[m * 32 + (a_k4 ^ (4 * (m & 7)))]) = pa[i];
        *reinterpret_cast<float4*>(&Bs[(w_k0 + i * 8) * 136 + w_n4]) = pw[i];
    }
    __syncthreads();

    const int sw = 4 * g;

    for (int kt = 0; kt < 512; kt += 32) {
        if (kt + 32 < 512) {
            #pragma unroll
            for (int i = 0; i < 4; i++) {
                const int row = mbase + a_m0 + i * 32;
                pa[i] = (row < M) ? *reinterpret_cast<const float4*>(&A[(size_t)row * 512 + kt + 32 + a_k4])
                                  : make_float4(0.f, 0.f, 0.f, 0.f);
                pw[i] = *reinterpret_cast<const float4*>(&W[(size_t)(kt + 32 + w_k0 + i * 8) * 512 + nbase + w_n4]);
            }
        }

        #pragma unroll
        for (int kb = 0; kb < 32; kb += 8) {
            uint32_t af[4][4], bf[4][2];
            #pragma unroll
            for (int mi = 0; mi < 4; mi++) {
                const int m0 = warp_m + mi * 16;
                const int k0 = (kb + tg) ^ sw;
                const int k1 = (kb + tg + 4) ^ sw;
                af[mi][0] = __float_as_uint(As[(m0 + g)     * 32 + k0]);
                af[mi][1] = __float_as_uint(As[(m0 + g + 8) * 32 + k0]);
                af[mi][2] = __float_as_uint(As[(m0 + g)     * 32 + k1]);
                af[mi][3] = __float_as_uint(As[(m0 + g + 8) * 32 + k1]);
            }
            #pragma unroll
            for (int ni = 0; ni < 4; ni++) {
                const int n_ = warp_n + ni * 8 + g;
                bf[ni][0] = __float_as_uint(Bs[(kb + tg)     * 136 + n_]);
                bf[ni][1] = __float_as_uint(Bs[(kb + tg + 4) * 136 + n_]);
            }
            #pragma unroll
            for (int mi = 0; mi < 4; mi++)
                #pragma unroll
                for (int ni = 0; ni < 4; ni++) {
                    asm volatile(
                        "mma.sync.aligned.m16n8k8.row.col.f32.tf32.tf32.f32 "
                        "{%0,%1,%2,%3}, {%4,%5,%6,%7}, {%8,%9}, {%0,%1,%2,%3};"
                        : "+f"(acc[mi][ni][0]), "+f"(acc[mi][ni][1]),
                          "+f"(acc[mi][ni][2]), "+f"(acc[mi][ni][3])
                        : "r"(af[mi][0]), "r"(af[mi][1]), "r"(af[mi][2]), "r"(af[mi][3]),
                          "r"(bf[ni][0]), "r"(bf[ni][1]));
                }
        }
        __syncthreads();
        if (kt + 32 < 512) {
            #pragma unroll
            for (int i = 0; i < 4; i++) {
                const int m = a_m0 + i * 32;
                *reinterpret_cast<float4*>(&As[m * 32 + (a_k4 ^ (4 * (m & 7)))]) = pa[i];
                *reinterpret_cast<float4*>(&Bs[(w_k0 + i * 8) * 136 + w_n4]) = pw[i];
            }
            __syncthreads();
        }
    }

    #pragma unroll
    for (int mi = 0; mi < 4; mi++) {
        const int r0 = mbase + warp_m + mi * 16 + g;
        const int r1 = r0 + 8;
        #pragma unroll
        for (int ni = 0; ni < 4; ni++) {
            const int c = nbase + warp_n + ni * 8 + tg * 2;
            const float2 bv2 = *reinterpret_cast<const float2*>(&bias[c]);
            if (r0 < M) {
                float2 o = make_float2(acc[mi][ni][0] + bv2.x, acc[mi][ni][1] + bv2.y);
                *reinterpret_cast<float2*>(&C[(size_t)r0 * 512 + c]) = o;
            }
            if (r1 < M) {
                float2 o = make_float2(acc[mi][ni][2] + bv2.x, acc[mi][ni][3] + bv2.y);
                *reinterpret_cast<float2*>(&C[(size_t)r1 * 512 + c]) = o;
            }
        }
    }
}

// ---------------------------------------------------------------------------
// Packed f32x2 helpers (sm_103a FFMA2 path — PTX-only)
// ---------------------------------------------------------------------------
typedef unsigned long long u64;

__device__ __forceinline__ u64 fma2(u64 a, u64 b, u64 c)
{ u64 d; asm("fma.rn.f32x2 %0, %1, %2, %3;" : "=l"(d) : "l"(a), "l"(b), "l"(c)); return d; }
__device__ __forceinline__ u64 mul2(u64 a, u64 b)
{ u64 d; asm("mul.rn.f32x2 %0, %1, %2;" : "=l"(d) : "l"(a), "l"(b)); return d; }
__device__ __forceinline__ u64 add2(u64 a, u64 b)
{ u64 d; asm("add.rn.f32x2 %0, %1, %2;" : "=l"(d) : "l"(a), "l"(b)); return d; }
__device__ __forceinline__ u64 pack2(float lo, float hi)
{ u64 d; asm("mov.b64 %0, {%1, %2};" : "=l"(d) : "f"(lo), "f"(hi)); return d; }
__device__ __forceinline__ void unpack2(u64 v, float& lo, float& hi)
{ asm("mov.b64 {%0, %1}, %2;" : "=f"(lo), "=f"(hi) : "l"(v)); }

__device__ __forceinline__ float ex2a(float x)
{ float r; asm("ex2.approx.f32 %0, %1;" : "=f"(r) : "f"(x)); return r; }
__device__ __forceinline__ float rcpa(float x)
{ float r; asm("rcp.approx.f32 %0, %1;" : "=f"(r) : "f"(x)); return r; }

#define TWO_LOG2E 2.8853900817779268f
#define ONE2_BITS 0x3F8000003F800000ULL

// Lane partial of S = sum_d wh[d] * r[d], r = 1/(2^m + 1), m = v*K + cgp.
// tanh fold: sum wh*tanh = Wsum - 2S (Wsum precomputed per lane).
// Two SIMD product trees (lo lanes / hi lanes) share one rcp pair per 8 elems.
__device__ __forceinline__ float zrow_wr(const float* __restrict__ r,
                                         const u64 K2, const u64 cgp[8], const u64 whp[8])
{
    u64 acc = 0ULL;   // (0.f, 0.f)
    #pragma unroll
    for (int h = 0; h < 2; h++) {
        const ulonglong2 u0 = *reinterpret_cast<const ulonglong2*>(&r[(2 * h) * 128]);
        const ulonglong2 u1 = *reinterpret_cast<const ulonglong2*>(&r[(2 * h + 1) * 128]);
        u64 m0 = fma2(u0.x, K2, cgp[4 * h + 0]);
        u64 m1 = fma2(u0.y, K2, cgp[4 * h + 1]);
        u64 m2 = fma2(u1.x, K2, cgp[4 * h + 2]);
        u64 m3 = fma2(u1.y, K2, cgp[4 * h + 3]);
        float a, b;
        u64 p0, p1, p2, p3;
        unpack2(m0, a, b); p0 = pack2(ex2a(a), ex2a(b));
        unpack2(m1, a, b); p1 = pack2(ex2a(a), ex2a(b));
        unpack2(m2, a, b); p2 = pack2(ex2a(a), ex2a(b));
        unpack2(m3, a, b); p3 = pack2(ex2a(a), ex2a(b));
        p0 = add2(p0, ONE2_BITS);
        p1 = add2(p1, ONE2_BITS);
        p2 = add2(p2, ONE2_BITS);
        p3 = add2(p3, ONE2_BITS);
        u64 t0 = mul2(p0, p1);
        u64 t1 = mul2(p2, p3);
        u64 T  = mul2(t0, t1);
        unpack2(T, a, b);
        u64 R   = pack2(rcpa(a), rcpa(b));
        u64 R01 = mul2(R, t1);   // (1/(p0p1))-per-SIMD-lane over the lo/hi trees
        u64 R23 = mul2(R, t0);
        acc = fma2(whp[4 * h + 0], mul2(R01, p1), acc);   // r of pair0
        acc = fma2(whp[4 * h + 1], mul2(R01, p0), acc);   // r of pair1
        acc = fma2(whp[4 * h + 2], mul2(R23, p3), acc);   // r of pair2
        acc = fma2(whp[4 * h + 3], mul2(R23, p2), acc);   // r of pair3
    }
    float lo, hi;
    unpack2(acc, lo, hi);
    return lo + hi;
}

// ---------------------------------------------------------------------------
// Fused kernel, one CTA per (b,t): grid = B*T = 4096, 128 threads (4 warps).
// Warps split k (stride-4). Warp 3 adds z_ext; warp 0 does softmax.
// All elementwise math in packed f32x2 (FFMA2).
// ---------------------------------------------------------------------------
__global__ __launch_bounds__(128)
void fused_attn_kernel(const float* __restrict__ V, const float* __restrict__ s_t,
                       const float* __restrict__ Wh, const float* __restrict__ bh,
                       float* __restrict__ out)
{
    __shared__ __align__(16) float part[4][512];
    __shared__ float z_s[52];
    __shared__ float alpha_s[52];
    __shared__ float beta_sh;

    const int tid  = threadIdx.x;
    const int lane = tid & 31;
    const int w    = tid >> 5;
    const int bt = blockIdx.x;
    const int b  = bt >> 8;            // bt / T_

    const u64 K2 = pack2(TWO_LOG2E, TWO_LOG2E);

    // cg (pre-scaled) and Wh as packed pairs; Wsum_lane for the tanh fold.
    u64 cgp[8], whp[8];
    float wsum = 0.f;
    {
        const float* __restrict__ cgrow = g_cg + (size_t)bt * 512 + lane * 4;
        const float* __restrict__ whrow = Wh + lane * 4;
        #pragma unroll
        for (int j = 0; j < 4; j++) {
            const ulonglong2 cu = *reinterpret_cast<const ulonglong2*>(&cgrow[j * 128]);
            const ulonglong2 wu = *reinterpret_cast<const ulonglong2*>(&whrow[j * 128]);
            cgp[2 * j]     = mul2(cu.x, K2);
            cgp[2 * j + 1] = mul2(cu.y, K2);
            whp[2 * j]     = wu.x;
            whp[2 * j + 1] = wu.y;
            float a, c;
            unpack2(wu.x, a, c); wsum += a + c;
            unpack2(wu.y, a, c); wsum += a + c;
        }
    }
    const float bhv = bh[0];

    const float* __restrict__ cvb = g_cv + (size_t)b * (K_ * 512) + lane * 4;

    // ---- z over this warp's k-subset: k = w, w+4, w+8, ... ----
    const int n = (K_ - w + 3) >> 2;   // 13,12,12,12
    int i = 0;
    for (; i + 1 < n; i += 2) {
        const int k0 = w + 4 * i;
        const int k1 = k0 + 4;
        float S0 = zrow_wr(cvb + (size_t)k0 * 512, K2, cgp, whp);
        float S1 = zrow_wr(cvb + (size_t)k1 * 512, K2, cgp, whp);
        float a0 = fmaf(-2.0f, S0, wsum);
        float a1 = fmaf(-2.0f, S1, wsum);
        #pragma unroll
        for (int o = 16; o > 0; o >>= 1) {
            a0 += __shfl_xor_sync(0xffffffffu, a0, o);
            a1 += __shfl_xor_sync(0xffffffffu, a1, o);
        }
        if (lane == 0) { z_s[k0] = a0 + bhv; z_s[k1] = a1 + bhv; }
    }
    if (i < n) {
        const int k0 = w + 4 * i;
        float S0 = zrow_wr(cvb + (size_t)k0 * 512, K2, cgp, whp);
        float a0 = fmaf(-2.0f, S0, wsum);
        #pragma unroll
        for (int o = 16; o > 0; o >>= 1)
            a0 += __shfl_xor_sync(0xffffffffu, a0, o);
        if (lane == 0) z_s[k0] = a0 + bhv;
    }

    // ---- z_ext (warp 3): content_s = cs_raw + cg ----
    if (w == 3) {
        float S = zrow_wr(g_cs + (size_t)bt * 512 + lane * 4, K2, cgp, whp);
        float acc = fmaf(-2.0f, S, wsum);
        #pragma unroll
        for (int o = 16; o > 0; o >>= 1)
            acc += __shfl_xor_sync(0xffffffffu, acc, o);
        if (lane == 0) z_s[K_] = acc + bhv;
    }
    __syncthreads();

    // ---- softmaxes (warp 0): alpha over 49, beta from extended 50 ----
    if (w == 0) {
        float z0 = (lane < K_)      ? z_s[lane]      : -1e30f;
        float z1 = (lane + 32 < K_) ? z_s[lane + 32] : -1e30f;
        float ze = z_s[K_];
        float m = fmaxf(fmaxf(z0, z1), ze);
        #pragma unroll
        for (int o = 16; o > 0; o >>= 1)
            m = fmaxf(m, __shfl_xor_sync(0xffffffffu, m, o));

        float e0 = (lane < K_)      ? __expf(z0 - m) : 0.f;
        float e1 = (lane + 32 < K_) ? __expf(z1 - m) : 0.f;
        float ee = __expf(ze - m);

        float s = e0 + e1;
        #pragma unroll
        for (int o = 16; o > 0; o >>= 1)
            s += __shfl_xor_sync(0xffffffffu, s, o);
        const float beta = ee / (s + ee);
        const float inv = 1.0f / s;

        if (lane < K_) {
            float a0 = e0 * inv;
            alpha_s[lane] = a0;
            out[OUT_ALPHA + (size_t)bt * K_ + lane] = a0;
        }
        if (lane + 32 < K_) {
            float a1 = e1 * inv;
            alpha_s[lane + 32] = a1;
            out[OUT_ALPHA + (size_t)bt * K_ + lane + 32] = a1;
        }
        if (lane == 0) {
            beta_sh = beta;
            out[OUT_BETA + bt] = beta;
        }
    }
    __syncthreads();

    // ---- c_t partial over this warp's k-subset (packed fma) ----
    u64 ca[8];
    #pragma unroll
    for (int j = 0; j < 8; j++) ca[j] = 0ULL;

    const float* __restrict__ Vb = V + (size_t)b * (K_ * 512) + lane * 4;
    i = 0;
    for (; i + 1 < n; i += 2) {
        const int k0 = w + 4 * i;
        const int k1 = k0 + 4;
        const u64 A0 = pack2(alpha_s[k0], alpha_s[k0]);
        const u64 A1 = pack2(alpha_s[k1], alpha_s[k1]);
        const float* __restrict__ r0 = Vb + (size_t)k0 * 512;
        const float* __restrict__ r1 = Vb + (size_t)k1 * 512;
        #pragma unroll
        for (int j = 0; j < 4; j++) {
            const ulonglong2 va = *reinterpret_cast<const ulonglong2*>(&r0[j * 128]);
            const ulonglong2 vb = *reinterpret_cast<const ulonglong2*>(&r1[j * 128]);
            ca[2 * j]     = fma2(A0, va.x, fma2(A1, vb.x, ca[2 * j]));
            ca[2 * j + 1] = fma2(A0, va.y, fma2(A1, vb.y, ca[2 * j + 1]));
        }
    }
    if (i < n) {
        const int k0 = w + 4 * i;
        const u64 A0 = pack2(alpha_s[k0], alpha_s[k0]);
        const float* __restrict__ r0 = Vb + (size_t)k0 * 512;
        #pragma unroll
        for (int j = 0; j < 4; j++) {
            const ulonglong2 va = *reinterpret_cast<const ulonglong2*>(&r0[j * 128]);
            ca[2 * j]     = fma2(A0, va.x, ca[2 * j]);
            ca[2 * j + 1] = fma2(A0, va.y, ca[2 * j + 1]);
        }
    }
    #pragma unroll
    for (int j = 0; j < 4; j++) {
        ulonglong2 st;
        st.x = ca[2 * j];
        st.y = ca[2 * j + 1];
        *reinterpret_cast<ulonglong2*>(&part[w][j * 128 + lane * 4]) = st;
    }
    __syncthreads();

    // ---- combine partials + blend: thread owns d in [4*tid, 4*tid+4) ----
    {
        const float beta = beta_sh;
        const int d = tid * 4;
        float4 p0 = *reinterpret_cast<const float4*>(&part[0][d]);
        float4 p1 = *reinterpret_cast<const float4*>(&part[1][d]);
        float4 p2 = *reinterpret_cast<const float4*>(&part[2][d]);
        float4 p3 = *reinterpret_cast<const float4*>(&part[3][d]);
        float4 c;
        c.x = (p0.x + p1.x) + (p2.x + p3.x);
        c.y = (p0.y + p1.y) + (p2.y + p3.y);
        c.z = (p0.z + p1.z) + (p2.z + p3.z);
        c.w = (p0.w + p1.w) + (p2.w + p3.w);
        float4 sv = *reinterpret_cast<const float4*>(&s_t[(size_t)bt * 512 + d]);
        float4 o;
        o.x = fmaf(beta, sv.x - c.x, c.x);
        o.y = fmaf(beta, sv.y - c.y, c.y);
        o.z = fmaf(beta, sv.z - c.z, c.z);
        o.w = fmaf(beta, sv.w - c.w, c.w);
        *reinterpret_cast<float4*>(&out[(size_t)bt * 512 + d]) = o;
    }
}

// ---------------------------------------------------------------------------
extern "C" void kernel_launch(void* const* d_in, const int* in_sizes, int n_in,
                              void* d_out, int out_size)
{
    (void)in_sizes; (void)n_in; (void)out_size;
    const float* V   = (const float*)d_in[0];
    const float* h_t = (const float*)d_in[1];
    const float* s_t = (const float*)d_in[2];
    const float* Wv  = (const float*)d_in[3];
    const float* bv  = (const float*)d_in[4];
    const float* Wg  = (const float*)d_in[5];
    const float* bg  = (const float*)d_in[6];
    const float* Ws  = (const float*)d_in[7];
    const float* bs  = (const float*)d_in[8];
    const float* Wh  = (const float*)d_in[9];
    const float* bh  = (const float*)d_in[10];
    float* out = (float*)d_out;

    gemm3_tf32_kernel<<<dim3(4, 71), 256>>>(V, h_t, s_t, Wv, bv, Wg, bg, Ws, bs);
    fused_attn_kernel<<<dim3(B_ * T_), 128>>>(V, s_t, Wh, bh, out);
}

// round 9
// speedup vs baseline: 1.1627x; 1.1627x over previous
#include <cuda_runtime.h>
#include <cstdint>

// Problem constants
#define B_ 16
#define K_ 49
#define T_ 256
#define H_ 512
#define D_ 512

// Output packing: (c_hat_t, alpha_t, beta_t) flattened in order
#define OUT_ALPHA (B_ * T_ * H_)              // 2097152
#define OUT_BETA  (OUT_ALPHA + B_ * T_ * K_)  // 2297856

// Scratch (device globals: allocation-free)
__device__ float g_cv[B_ * K_ * D_];   // V @ Wv + bv
__device__ float g_cg[B_ * T_ * D_];   // h_t @ Wg + bg
__device__ float g_cs[B_ * T_ * D_];   // s_t @ Ws + bs

// ---------------------------------------------------------------------------
// Merged TF32 mma.sync GEMM: computes all three C[M,512] = A[M,512]@W + bias.
// ---------------------------------------------------------------------------
__global__ __launch_bounds__(256)
void gemm3_tf32_kernel(const float* __restrict__ V, const float* __restrict__ h_t,
                       const float* __restrict__ s_t,
                       const float* __restrict__ Wv, const float* __restrict__ bv,
                       const float* __restrict__ Wg, const float* __restrict__ bg,
                       const float* __restrict__ Wss, const float* __restrict__ bss)
{
    __shared__ float As[128 * 32];     // [m][k], k index xor-swizzled by 4*(m&7)
    __shared__ float Bs[32 * 136];     // [k][n], row stride 136 (pad 8)

    const int nt = blockIdx.x;         // 0..3
    int mt = blockIdx.y;               // 0..70
    const float *A, *W, *bias;
    float* C;
    int M;
    if (mt < 7)       { A = V;   W = Wv;  bias = bv;  C = g_cv; M = B_ * K_; }
    else if (mt < 39) { A = h_t; W = Wg;  bias = bg;  C = g_cg; M = B_ * T_; mt -= 7; }
    else              { A = s_t; W = Wss; bias = bss; C = g_cs; M = B_ * T_; mt -= 39; }

    const int tid  = threadIdx.x;
    const int lane = tid & 31;
    const int wid  = tid >> 5;
    const int g    = lane >> 2;
    const int tg   = lane & 3;
    const int warp_m = (wid >> 2) * 64;
    const int warp_n = (wid & 3) * 32;

    const int mbase = mt * 128;
    const int nbase = nt * 128;

    float acc[4][4][4];
    #pragma unroll
    for (int i = 0; i < 4; i++)
        #pragma unroll
        for (int j = 0; j < 4; j++)
            #pragma unroll
            for (int q = 0; q < 4; q++) acc[i][j][q] = 0.f;

    const int a_m0 = tid >> 3;
    const int a_k4 = (tid & 7) * 4;
    const int w_k0 = tid >> 5;
    const int w_n4 = (tid & 31) * 4;

    float4 pa[4], pw[4];

    #pragma unroll
    for (int i = 0; i < 4; i++) {
        const int row = mbase + a_m0 + i * 32;
        pa[i] = (row < M) ? *reinterpret_cast<const float4*>(&A[(size_t)row * 512 + a_k4])
                          : make_float4(0.f, 0.f, 0.f, 0.f);
        pw[i] = *reinterpret_cast<const float4*>(&W[(size_t)(w_k0 + i * 8) * 512 + nbase + w_n4]);
    }
    #pragma unroll
    for (int i = 0; i < 4; i++) {
        const int m = a_m0 + i * 32;
        *reinterpret_cast<float4*>(&As[m * 32 + (a_k4 ^ (4 * (m & 7)))]) = pa[i];
        *reinterpret_cast<float4*>(&Bs[(w_k0 + i * 8) * 136 + w_n4]) = pw[i];
    }
    __syncthreads();

    const int sw = 4 * g;

    for (int kt = 0; kt < 512; kt += 32) {
        if (kt + 32 < 512) {
            #pragma unroll
            for (int i = 0; i < 4; i++) {
                const int row = mbase + a_m0 + i * 32;
                pa[i] = (row < M) ? *reinterpret_cast<const float4*>(&A[(size_t)row * 512 + kt + 32 + a_k4])
                                  : make_float4(0.f, 0.f, 0.f, 0.f);
                pw[i] = *reinterpret_cast<const float4*>(&W[(size_t)(kt + 32 + w_k0 + i * 8) * 512 + nbase + w_n4]);
            }
        }

        #pragma unroll
        for (int kb = 0; kb < 32; kb += 8) {
            uint32_t af[4][4], bf[4][2];
            #pragma unroll
            for (int mi = 0; mi < 4; mi++) {
                const int m0 = warp_m + mi * 16;
                const int k0 = (kb + tg) ^ sw;
                const int k1 = (kb + tg + 4) ^ sw;
                af[mi][0] = __float_as_uint(As[(m0 + g)     * 32 + k0]);
                af[mi][1] = __float_as_uint(As[(m0 + g + 8) * 32 + k0]);
                af[mi][2] = __float_as_uint(As[(m0 + g)     * 32 + k1]);
                af[mi][3] = __float_as_uint(As[(m0 + g + 8) * 32 + k1]);
            }
            #pragma unroll
            for (int ni = 0; ni < 4; ni++) {
                const int n_ = warp_n + ni * 8 + g;
                bf[ni][0] = __float_as_uint(Bs[(kb + tg)     * 136 + n_]);
                bf[ni][1] = __float_as_uint(Bs[(kb + tg + 4) * 136 + n_]);
            }
            #pragma unroll
            for (int mi = 0; mi < 4; mi++)
                #pragma unroll
                for (int ni = 0; ni < 4; ni++) {
                    asm volatile(
                        "mma.sync.aligned.m16n8k8.row.col.f32.tf32.tf32.f32 "
                        "{%0,%1,%2,%3}, {%4,%5,%6,%7}, {%8,%9}, {%0,%1,%2,%3};"
                        : "+f"(acc[mi][ni][0]), "+f"(acc[mi][ni][1]),
                          "+f"(acc[mi][ni][2]), "+f"(acc[mi][ni][3])
                        : "r"(af[mi][0]), "r"(af[mi][1]), "r"(af[mi][2]), "r"(af[mi][3]),
                          "r"(bf[ni][0]), "r"(bf[ni][1]));
                }
        }
        __syncthreads();
        if (kt + 32 < 512) {
            #pragma unroll
            for (int i = 0; i < 4; i++) {
                const int m = a_m0 + i * 32;
                *reinterpret_cast<float4*>(&As[m * 32 + (a_k4 ^ (4 * (m & 7)))]) = pa[i];
                *reinterpret_cast<float4*>(&Bs[(w_k0 + i * 8) * 136 + w_n4]) = pw[i];
            }
            __syncthreads();
        }
    }

    #pragma unroll
    for (int mi = 0; mi < 4; mi++) {
        const int r0 = mbase + warp_m + mi * 16 + g;
        const int r1 = r0 + 8;
        #pragma unroll
        for (int ni = 0; ni < 4; ni++) {
            const int c = nbase + warp_n + ni * 8 + tg * 2;
            const float2 bv2 = *reinterpret_cast<const float2*>(&bias[c]);
            if (r0 < M) {
                float2 o = make_float2(acc[mi][ni][0] + bv2.x, acc[mi][ni][1] + bv2.y);
                *reinterpret_cast<float2*>(&C[(size_t)r0 * 512 + c]) = o;
            }
            if (r1 < M) {
                float2 o = make_float2(acc[mi][ni][2] + bv2.x, acc[mi][ni][3] + bv2.y);
                *reinterpret_cast<float2*>(&C[(size_t)r1 * 512 + c]) = o;
            }
        }
    }
}

// Single-MUFU tanh (MUFU.TANH). Max abs err ~5e-4 — washes out at 1e-3 gate.
__device__ __forceinline__ float tanha(float x)
{
    float r;
    asm("tanh.approx.f32 %0, %1;" : "=f"(r) : "f"(x));
    return r;
}

// One z-row lane partial: sum_d tanh(row[d] + cg[d]) * Wh[d].
// Minimal per-element cost: 1 FADD + 1 MUFU + 1 FFMA.
__device__ __forceinline__ float z_row(const float* __restrict__ r,
                                       const float4 cg[4], const float4 wh[4])
{
    float acc = 0.f;
    #pragma unroll
    for (int j = 0; j < 4; j++) {
        float4 v = *reinterpret_cast<const float4*>(&r[j * 128]);
        acc = fmaf(tanha(v.x + cg[j].x), wh[j].x, acc);
        acc = fmaf(tanha(v.y + cg[j].y), wh[j].y, acc);
        acc = fmaf(tanha(v.z + cg[j].z), wh[j].z, acc);
        acc = fmaf(tanha(v.w + cg[j].w), wh[j].w, acc);
    }
    return acc;
}

// ---------------------------------------------------------------------------
// Fused kernel, one CTA per (b,t): grid = B*T = 4096, 128 threads (4 warps).
// Warps split k (stride-4, 13/12/12/12). Warp 3 adds z_ext; warp 0 softmax.
// c_t as 4 per-warp partials combined in smem. part[] 16B-aligned.
// ---------------------------------------------------------------------------
__global__ __launch_bounds__(128, 8)
void fused_attn_kernel(const float* __restrict__ V, const float* __restrict__ s_t,
                       const float* __restrict__ Wh, const float* __restrict__ bh,
                       float* __restrict__ out)
{
    __shared__ __align__(16) float part[4][512];
    __shared__ float z_s[52];
    __shared__ float alpha_s[52];
    __shared__ float beta_sh;

    const int tid  = threadIdx.x;
    const int lane = tid & 31;
    const int w    = tid >> 5;
    const int bt = blockIdx.x;
    const int b  = bt >> 8;            // bt / T_

    // cg row (raw) and Wh: register-resident. d = 128j + 4*lane + c.
    float4 cg[4], wh[4];
    {
        const float* __restrict__ cgrow = g_cg + (size_t)bt * 512 + lane * 4;
        const float* __restrict__ whrow = Wh + lane * 4;
        #pragma unroll
        for (int j = 0; j < 4; j++) {
            cg[j] = *reinterpret_cast<const float4*>(&cgrow[j * 128]);
            wh[j] = *reinterpret_cast<const float4*>(&whrow[j * 128]);
        }
    }
    const float bhv = bh[0];

    const float* __restrict__ cvb = g_cv + (size_t)b * (K_ * 512) + lane * 4;

    // ---- z over this warp's k-subset: k = w, w+4, w+8, ... ----
    const int n = (K_ - w + 3) >> 2;   // 13,12,12,12
    int i = 0;
    for (; i + 1 < n; i += 2) {
        const int k0 = w + 4 * i;
        const int k1 = k0 + 4;
        float a0 = z_row(cvb + (size_t)k0 * 512, cg, wh);
        float a1 = z_row(cvb + (size_t)k1 * 512, cg, wh);
        #pragma unroll
        for (int o = 16; o > 0; o >>= 1) {
            a0 += __shfl_xor_sync(0xffffffffu, a0, o);
            a1 += __shfl_xor_sync(0xffffffffu, a1, o);
        }
        if (lane == 0) { z_s[k0] = a0 + bhv; z_s[k1] = a1 + bhv; }
    }
    if (i < n) {
        const int k0 = w + 4 * i;
        float a0 = z_row(cvb + (size_t)k0 * 512, cg, wh);
        #pragma unroll
        for (int o = 16; o > 0; o >>= 1)
            a0 += __shfl_xor_sync(0xffffffffu, a0, o);
        if (lane == 0) z_s[k0] = a0 + bhv;
    }

    // ---- z_ext (warp 3): content_s = cs_raw + cg ----
    if (w == 3) {
        float acc = z_row(g_cs + (size_t)bt * 512 + lane * 4, cg, wh);
        #pragma unroll
        for (int o = 16; o > 0; o >>= 1)
            acc += __shfl_xor_sync(0xffffffffu, acc, o);
        if (lane == 0) z_s[K_] = acc + bhv;
    }
    __syncthreads();

    // ---- softmaxes (warp 0): alpha over 49, beta from extended 50 ----
    if (w == 0) {
        float z0 = (lane < K_)      ? z_s[lane]      : -1e30f;
        float z1 = (lane + 32 < K_) ? z_s[lane + 32] : -1e30f;
        float ze = z_s[K_];
        float m = fmaxf(fmaxf(z0, z1), ze);
        #pragma unroll
        for (int o = 16; o > 0; o >>= 1)
            m = fmaxf(m, __shfl_xor_sync(0xffffffffu, m, o));

        float e0 = (lane < K_)      ? __expf(z0 - m) : 0.f;
        float e1 = (lane + 32 < K_) ? __expf(z1 - m) : 0.f;
        float ee = __expf(ze - m);

        float s = e0 + e1;
        #pragma unroll
        for (int o = 16; o > 0; o >>= 1)
            s += __shfl_xor_sync(0xffffffffu, s, o);
        const float beta = ee / (s + ee);
        const float inv = 1.0f / s;

        if (lane < K_) {
            float a0 = e0 * inv;
            alpha_s[lane] = a0;
            out[OUT_ALPHA + (size_t)bt * K_ + lane] = a0;
        }
        if (lane + 32 < K_) {
            float a1 = e1 * inv;
            alpha_s[lane + 32] = a1;
            out[OUT_ALPHA + (size_t)bt * K_ + lane + 32] = a1;
        }
        if (lane == 0) {
            beta_sh = beta;
            out[OUT_BETA + bt] = beta;
        }
    }
    __syncthreads();

    // ---- c_t partial over this warp's k-subset ----
    float4 cacc[4];
    #pragma unroll
    for (int j = 0; j < 4; j++) cacc[j] = make_float4(0.f, 0.f, 0.f, 0.f);

    const float* __restrict__ Vb = V + (size_t)b * (K_ * 512) + lane * 4;
    i = 0;
    for (; i + 1 < n; i += 2) {
        const int k0 = w + 4 * i;
        const int k1 = k0 + 4;
        const float a0 = alpha_s[k0];
        const float a1 = alpha_s[k1];
        const float* __restrict__ r0 = Vb + (size_t)k0 * 512;
        const float* __restrict__ r1 = Vb + (size_t)k1 * 512;
        #pragma unroll
        for (int j = 0; j < 4; j++) {
            float4 va = *reinterpret_cast<const float4*>(&r0[j * 128]);
            float4 vb = *reinterpret_cast<const float4*>(&r1[j * 128]);
            cacc[j].x = fmaf(a0, va.x, fmaf(a1, vb.x, cacc[j].x));
            cacc[j].y = fmaf(a0, va.y, fmaf(a1, vb.y, cacc[j].y));
            cacc[j].z = fmaf(a0, va.z, fmaf(a1, vb.z, cacc[j].z));
            cacc[j].w = fmaf(a0, va.w, fmaf(a1, vb.w, cacc[j].w));
        }
    }
    if (i < n) {
        const int k0 = w + 4 * i;
        const float a0 = alpha_s[k0];
        const float* __restrict__ r0 = Vb + (size_t)k0 * 512;
        #pragma unroll
        for (int j = 0; j < 4; j++) {
            float4 va = *reinterpret_cast<const float4*>(&r0[j * 128]);
            cacc[j].x = fmaf(a0, va.x, cacc[j].x);
            cacc[j].y = fmaf(a0, va.y, cacc[j].y);
            cacc[j].z = fmaf(a0, va.z, cacc[j].z);
            cacc[j].w = fmaf(a0, va.w, cacc[j].w);
        }
    }
    #pragma unroll
    for (int j = 0; j < 4; j++)
        *reinterpret_cast<float4*>(&part[w][j * 128 + lane * 4]) = cacc[j];
    __syncthreads();

    // ---- combine partials + blend: thread owns d in [4*tid, 4*tid+4) ----
    {
        const float beta = beta_sh;
        const int d = tid * 4;
        float4 p0 = *reinterpret_cast<const float4*>(&part[0][d]);
        float4 p1 = *reinterpret_cast<const float4*>(&part[1][d]);
        float4 p2 = *reinterpret_cast<const float4*>(&part[2][d]);
        float4 p3 = *reinterpret_cast<const float4*>(&part[3][d]);
        float4 c;
        c.x = (p0.x + p1.x) + (p2.x + p3.x);
        c.y = (p0.y + p1.y) + (p2.y + p3.y);
        c.z = (p0.z + p1.z) + (p2.z + p3.z);
        c.w = (p0.w + p1.w) + (p2.w + p3.w);
        float4 sv = *reinterpret_cast<const float4*>(&s_t[(size_t)bt * 512 + d]);
        float4 o;
        o.x = fmaf(beta, sv.x - c.x, c.x);
        o.y = fmaf(beta, sv.y - c.y, c.y);
        o.z = fmaf(beta, sv.z - c.z, c.z);
        o.w = fmaf(beta, sv.w - c.w, c.w);
        *reinterpret_cast<float4*>(&out[(size_t)bt * 512 + d]) = o;
    }
}

// ---------------------------------------------------------------------------
extern "C" void kernel_launch(void* const* d_in, const int* in_sizes, int n_in,
                              void* d_out, int out_size)
{
    (void)in_sizes; (void)n_in; (void)out_size;
    const float* V   = (const float*)d_in[0];
    const float* h_t = (const float*)d_in[1];
    const float* s_t = (const float*)d_in[2];
    const float* Wv  = (const float*)d_in[3];
    const float* bv  = (const float*)d_in[4];
    const float* Wg  = (const float*)d_in[5];
    const float* bg  = (const float*)d_in[6];
    const float* Ws  = (const float*)d_in[7];
    const float* bs  = (const float*)d_in[8];
    const float* Wh  = (const float*)d_in[9];
    const float* bh  = (const float*)d_in[10];
    float* out = (float*)d_out;

    gemm3_tf32_kernel<<<dim3(4, 71), 256>>>(V, h_t, s_t, Wv, bv, Wg, bg, Ws, bs);
    fused_attn_kernel<<<dim3(B_ * T_), 128>>>(V, s_t, Wh, bh, out);
}